// round 15
// baseline (speedup 1.0000x reference)
#include <cuda_runtime.h>
#include <cuda_bf16.h>

#define D 128
#define MAXN 50176
#define TM 64
#define NB 16384          // bytes per B buffer (128x64 bf16)
#define WC_BASE 65536     // Wc persistent buffers base (edge kernel)
#define XB_EDGE 131072    // XCH base in edge kernel
#define XB_NODE 65536     // XCH base in node/pre kernels
#define SMEM_EDGE (131072 + 256 * 144)
#define SMEM_NODE (65536 + 256 * 144)
#define SMEM_PRE 65536

typedef unsigned uns;

__device__ float g_agg[MAXN * D];
__device__ float g_tsum[MAXN * 3];
__device__ float g_cnt[MAXN];
__device__ float g_Hr[MAXN * D];   // h @ We1[0:128]
__device__ float g_Hc[MAXN * D];   // h @ We1[128:256]

// prepped W^T bf16 hi/lo: [chunk][n=128][kc=64]
__device__ __nv_bfloat16 g_W1H[4 * 8192], g_W1L[4 * 8192];
__device__ __nv_bfloat16 g_W2H[2 * 8192], g_W2L[2 * 8192];
__device__ __nv_bfloat16 g_WcH[2 * 8192], g_WcL[2 * 8192];
__device__ __nv_bfloat16 g_N1H[4 * 8192], g_N1L[4 * 8192];
__device__ __nv_bfloat16 g_N2H[2 * 8192], g_N2L[2 * 8192];
__device__ float g_W1last[128];

__device__ __forceinline__ float silu_f(float x) { return x / (1.0f + __expf(-x)); }
__device__ __forceinline__ uns sw128(uns o) { return o ^ ((o >> 3) & 0x70); }

__device__ __forceinline__ uns smem_u32(const void* p) {
    uns a;
    asm("{ .reg .u64 t; cvta.to.shared.u64 t, %1; cvt.u32.u64 %0, t; }" : "=r"(a) : "l"(p));
    return a;
}
__device__ __forceinline__ void split2(float a, float b, uns& hi, uns& lo) {
    uns p;
    asm("cvt.rn.satfinite.bf16x2.f32 %0, %1, %2;" : "=r"(p) : "f"(b), "f"(a));
    float f0 = __uint_as_float(p << 16);
    float f1 = __uint_as_float(p & 0xFFFF0000u);
    uns q;
    asm("cvt.rn.satfinite.bf16x2.f32 %0, %1, %2;" : "=r"(q) : "f"(b - f1), "f"(a - f0));
    hi = p; lo = q;
}
__device__ __forceinline__ void ldm_x2(uns r[2], uns addr) {
    asm volatile("ldmatrix.sync.aligned.m8n8.x2.shared.b16 {%0,%1}, [%2];"
        : "=r"(r[0]), "=r"(r[1]) : "r"(addr));
}
__device__ __forceinline__ void mma16816(float c[4], const uns a[4], const uns b[2]) {
    asm volatile("mma.sync.aligned.m16n8k16.row.col.f32.bf16.bf16.f32 "
        "{%0,%1,%2,%3}, {%4,%5,%6,%7}, {%8,%9}, {%0,%1,%2,%3};"
        : "+f"(c[0]), "+f"(c[1]), "+f"(c[2]), "+f"(c[3])
        : "r"(a[0]), "r"(a[1]), "r"(a[2]), "r"(a[3]), "r"(b[0]), "r"(b[1]));
}

// ------------------------------------------------------------------
__global__ void __launch_bounds__(256) zero_kernel(int N) {
    int i = blockIdx.x * blockDim.x + threadIdx.x;
    int stride = gridDim.x * blockDim.x;
    for (int k = i; k < N * D; k += stride) g_agg[k] = 0.0f;
    for (int k = i; k < N * 3; k += stride) g_tsum[k] = 0.0f;
    for (int k = i; k < N; k += stride) g_cnt[k] = 0.0f;
}

__global__ void __launch_bounds__(512) prep_kernel(
    const float* __restrict__ We1, const float* __restrict__ We2,
    const float* __restrict__ Wc1, const float* __restrict__ Wn1,
    const float* __restrict__ Wn2)
{
    int id = blockIdx.x * blockDim.x + threadIdx.x;  // 0..32767
    int c = id >> 13, r = id & 8191, n = r >> 6, kc = r & 63;
    int src = (c * 64 + kc) * 128 + n;
    {
        float f = We1[src];
        __nv_bfloat16 hv = __float2bfloat16(f);
        g_W1H[id] = hv; g_W1L[id] = __float2bfloat16(f - __bfloat162float(hv));
        float fn = Wn1[src];
        __nv_bfloat16 hn = __float2bfloat16(fn);
        g_N1H[id] = hn; g_N1L[id] = __float2bfloat16(fn - __bfloat162float(hn));
    }
    if (id < 2 * 8192) {
        float f = We2[src];
        __nv_bfloat16 hv = __float2bfloat16(f);
        g_W2H[id] = hv; g_W2L[id] = __float2bfloat16(f - __bfloat162float(hv));
        float g = Wc1[src];
        __nv_bfloat16 hg = __float2bfloat16(g);
        g_WcH[id] = hg; g_WcL[id] = __float2bfloat16(g - __bfloat162float(hg));
        float fn = Wn2[src];
        __nv_bfloat16 hn = __float2bfloat16(fn);
        g_N2H[id] = hn; g_N2L[id] = __float2bfloat16(fn - __bfloat162float(hn));
    }
    if (id < 128) g_W1last[id] = We1[256 * 128 + id];
}

// ---- common macros (t, su, smB, b_row, ntg0, acc in scope) ----
// async load of one weight chunk (hi+lo) into buffer `buf` at region `base`
#define LOADB_A(gH, gL, c, buf, base)                                         \
    {                                                                         \
        _Pragma("unroll")                                                     \
        for (int i0 = 0; i0 < 4; i0++) {                                      \
            int i = t + i0 * 256;                                             \
            uns dst = sw128((uns)((i >> 3) * 128 + (i & 7) * 16));            \
            const uint4* s1 = (const uint4*)(gH) + (c) * 1024 + i;            \
            const uint4* s2 = (const uint4*)(gL) + (c) * 1024 + i;            \
            asm volatile("cp.async.cg.shared.global [%0], [%1], 16;"          \
                :: "r"(su + (base) + (buf) * NB + dst),                       \
                   "l"((unsigned long long)__cvta_generic_to_global(s1)) : "memory"); \
            asm volatile("cp.async.cg.shared.global [%0], [%1], 16;"          \
                :: "r"(su + (base) + 2 * NB + (buf) * NB + dst),              \
                   "l"((unsigned long long)__cvta_generic_to_global(s2)) : "memory"); \
        }                                                                     \
        asm volatile("cp.async.commit_group;" ::: "memory");                  \
    }

#define CP_WAIT(n) asm volatile("cp.async.wait_group %0;" :: "n"(n) : "memory")

// 8 nt-tiles (64 cols), 2 groups of 4, B regs reused between hi/lo phases
#define MMA_NT8(ah, al, bufb, base)                                           \
    _Pragma("unroll")                                                         \
    for (int ng = 0; ng < 2; ng++) {                                          \
        uns b4[4][2];                                                         \
        _Pragma("unroll")                                                     \
        for (int j = 0; j < 4; j++) {                                         \
            uns bsw = sw128(b_row + (uns)((ntg0 + ng * 4 + j) * 1024) + (uns)(ks * 32)); \
            ldm_x2(b4[j], su + (base) + (bufb) * NB + bsw);                   \
        }                                                                     \
        _Pragma("unroll")                                                     \
        for (int j = 0; j < 4; j++) mma16816(acc[ng * 4 + j], ah, b4[j]);     \
        _Pragma("unroll")                                                     \
        for (int j = 0; j < 4; j++) mma16816(acc[ng * 4 + j], al, b4[j]);     \
        _Pragma("unroll")                                                     \
        for (int j = 0; j < 4; j++) {                                         \
            uns bsw = sw128(b_row + (uns)((ntg0 + ng * 4 + j) * 1024) + (uns)(ks * 32)); \
            ldm_x2(b4[j], su + (base) + 2 * NB + (bufb) * NB + bsw);          \
        }                                                                     \
        _Pragma("unroll")                                                     \
        for (int j = 0; j < 4; j++) mma16816(acc[ng * 4 + j], ah, b4[j]);     \
    }

#define ACC_ZERO8()                                                           \
    _Pragma("unroll")                                                         \
    for (int nt = 0; nt < 8; nt++)                                            \
        _Pragma("unroll")                                                     \
        for (int j = 0; j < 4; j++) acc[nt][j] = 0.0f;

#define A_FRAGS_FROM_GLOBAL(pA, pB, k0, ah, al)                               \
    {                                                                         \
        float2 vA0 = *(const float2*)((pA) + (k0));                           \
        float2 vA1 = *(const float2*)((pA) + (k0) + 8);                       \
        float2 vB0 = *(const float2*)((pB) + (k0));                           \
        float2 vB1 = *(const float2*)((pB) + (k0) + 8);                       \
        split2(vA0.x, vA0.y, ah[0], al[0]);                                   \
        split2(vB0.x, vB0.y, ah[1], al[1]);                                   \
        split2(vA1.x, vA1.y, ah[2], al[2]);                                   \
        split2(vB1.x, vB1.y, ah[3], al[3]);                                   \
    }

// layer-1-style chunk: A from global rows, k-offset = (c&1)*64; base 0
#define L1_CHUNK(c, bufb, pA, pB)                                             \
    _Pragma("unroll")                                                         \
    for (int ks = 0; ks < 4; ks++) {                                          \
        uns ah[4], al[4];                                                     \
        A_FRAGS_FROM_GLOBAL(pA, pB, ((c) & 1) * 64 + 2 * tq + ks * 16, ah, al); \
        MMA_NT8(ah, al, bufb, 0);                                             \
    }

// XCH-layer chunk: A frags from exchange region at XBv, B from `base`
#define X_CHUNK(c, base)                                                      \
    _Pragma("unroll")                                                         \
    for (int ks = 0; ks < 4; ks++) {                                          \
        const int kt = (c) * 4 + ks;                                          \
        const int owner = (t & ~32) | (((c) & 1) << 5);                       \
        const char* xp = smB + XBv + owner * 144 + (kt & 3) * 16;             \
        uint4 hv = *(const uint4*)xp;                                         \
        uint4 lv = *(const uint4*)(xp + 64);                                  \
        uns ah[4] = {hv.x, hv.y, hv.z, hv.w};                                 \
        uns al[4] = {lv.x, lv.y, lv.z, lv.w};                                 \
        MMA_NT8(ah, al, (c), base);                                           \
    }

#define XCH_STORE(ntg, x0, x1, x2, x3)                                        \
    {                                                                         \
        uns h0, l0, h1, l1;                                                   \
        split2(x0, x1, h0, l0);                                               \
        split2(x2, x3, h1, l1);                                               \
        char* xp = smB + XBv + t * 144 + ((((ntg) >> 1) & 3) * 16) + (((ntg) & 1) * 8); \
        *(uint2*)xp = make_uint2(h0, h1);                                     \
        *(uint2*)(xp + 64) = make_uint2(l0, l1);                              \
    }

// ------------------------------------------------------------------
// per-node precompute: Hr = h @ We1[0:128], Hc = h @ We1[128:256]
__global__ void __launch_bounds__(256, 2) pre_h_kernel(
    const float* __restrict__ h, int N)
{
    extern __shared__ __align__(1024) char smB[];
    const uns su = smem_u32(smB);
    const int t = threadIdx.x;
    const int w = t >> 5, l = t & 31;
    const int g = l >> 2, tq = l & 3;
    const int strip = w >> 1, nhalf = w & 1;
    const int ntg0 = nhalf * 8;
    const int n0 = blockIdx.x * TM;
    const uns b_row = (uns)((l & 7) * 128 + ((l >> 3) & 1) * 16);

    LOADB_A(g_W1H, g_W1L, 0, 0, 0);
    LOADB_A(g_W1H, g_W1L, 1, 1, 0);

    const int r0 = strip * 16 + g, r1 = r0 + 8;
    const int nA = min(n0 + r0, N - 1), nB = min(n0 + r1, N - 1);
    const bool v0 = (n0 + r0) < N, v1 = (n0 + r1) < N;
    const float* pH0 = h + (size_t)nA * 128;
    const float* pH1 = h + (size_t)nB * 128;

    float acc[8][4];

    // ---- Hr (weight chunks 0,1) ----
    ACC_ZERO8();
    CP_WAIT(1); __syncthreads();
    L1_CHUNK(0, 0, pH0, pH1);
    __syncthreads();
    LOADB_A(g_W1H, g_W1L, 2, 0, 0);
    CP_WAIT(1); __syncthreads();
    L1_CHUNK(1, 1, pH0, pH1);
    {
        #pragma unroll
        for (int nt = 0; nt < 8; nt++) {
            int c0 = (ntg0 + nt) * 8 + 2 * tq;
            if (v0) *(float2*)(g_Hr + (size_t)nA * 128 + c0) = make_float2(acc[nt][0], acc[nt][1]);
            if (v1) *(float2*)(g_Hr + (size_t)nB * 128 + c0) = make_float2(acc[nt][2], acc[nt][3]);
        }
    }
    __syncthreads();
    LOADB_A(g_W1H, g_W1L, 3, 1, 0);

    // ---- Hc (weight chunks 2,3) ----
    ACC_ZERO8();
    CP_WAIT(1); __syncthreads();
    L1_CHUNK(0, 0, pH0, pH1);
    CP_WAIT(0); __syncthreads();
    L1_CHUNK(1, 1, pH0, pH1);
    {
        #pragma unroll
        for (int nt = 0; nt < 8; nt++) {
            int c0 = (ntg0 + nt) * 8 + 2 * tq;
            if (v0) *(float2*)(g_Hc + (size_t)nA * 128 + c0) = make_float2(acc[nt][0], acc[nt][1]);
            if (v1) *(float2*)(g_Hc + (size_t)nB * 128 + c0) = make_float2(acc[nt][2], acc[nt][3]);
        }
    }
}

// persistent-weight multi-tile edge kernel (1 CTA/SM)
__global__ void __launch_bounds__(256, 1) edge_tc_kernel(
    const int* __restrict__ ei, const float* __restrict__ coord,
    const float* __restrict__ be1, const float* __restrict__ be2,
    const float* __restrict__ Watt, const float* __restrict__ batt,
    const float* __restrict__ bc1, const float* __restrict__ Wc2,
    float* __restrict__ out_ef, int E, int nTiles)
{
    extern __shared__ __align__(1024) char smB[];  // [W2 hi/lo][Wc hi/lo][xch]
    __shared__ int s_row[TM], s_col[TM];
    __shared__ float s_rad[TM], s_cd[TM * 3];
    __shared__ float s_red[8][8][2];

    const uns su = smem_u32(smB);
    const int XBv = XB_EDGE;
    const int t = threadIdx.x;
    const int w = t >> 5, l = t & 31;
    const int g = l >> 2, tq = l & 3;
    const int strip = w >> 1, nhalf = w & 1;
    const int ntg0 = nhalf * 8;
    const uns b_row = (uns)((l & 7) * 128 + ((l >> 3) & 1) * 16);

    // load ALL weights once (4 chunk-pairs: W2 c0,c1 + Wc c0,c1)
    LOADB_A(g_W2H, g_W2L, 0, 0, 0);
    LOADB_A(g_W2H, g_W2L, 1, 1, 0);
    LOADB_A(g_WcH, g_WcL, 0, 0, WC_BASE);
    LOADB_A(g_WcH, g_WcL, 1, 1, WC_BASE);
    CP_WAIT(0);
    __syncthreads();

    const int r0 = strip * 16 + g, r1 = r0 + 8;
    float acc[8][4];

    for (int tile = blockIdx.x; tile < nTiles; tile += gridDim.x) {
        const int e0 = tile * TM;
        __syncthreads();   // prior tile fully done (s_row/s_cd/XCH readers)

        if (t < TM) {
            int e = min(e0 + t, E - 1);
            int r = ei[e], c = ei[(size_t)E + e];
            s_row[t] = r; s_col[t] = c;
            float dx = coord[r * 3 + 0] - coord[c * 3 + 0];
            float dy = coord[r * 3 + 1] - coord[c * 3 + 1];
            float dz = coord[r * 3 + 2] - coord[c * 3 + 2];
            s_cd[t * 3 + 0] = dx; s_cd[t * 3 + 1] = dy; s_cd[t * 3 + 2] = dz;
            s_rad[t] = dx * dx + dy * dy + dz * dz;
        }
        __syncthreads();

        const bool v0 = (e0 + r0) < E, v1 = (e0 + r1) < E;

        // ===== layer1 via gather: silu(Hr[row]+Hc[col]+be1+rad*W1last) -> XCH
        {
            const float* hr0 = g_Hr + (size_t)s_row[r0] * 128;
            const float* hc0 = g_Hc + (size_t)s_col[r0] * 128;
            const float* hr1 = g_Hr + (size_t)s_row[r1] * 128;
            const float* hc1 = g_Hc + (size_t)s_col[r1] * 128;
            float rad0 = s_rad[r0], rad1 = s_rad[r1];
            #pragma unroll
            for (int nt = 0; nt < 8; nt++) {
                int ntg = ntg0 + nt;
                int c0 = ntg * 8 + 2 * tq;
                float2 aR0 = *(const float2*)(hr0 + c0);
                float2 aC0 = *(const float2*)(hc0 + c0);
                float2 aR1 = *(const float2*)(hr1 + c0);
                float2 aC1 = *(const float2*)(hc1 + c0);
                float w0 = g_W1last[c0], w1 = g_W1last[c0 + 1];
                float b0 = __ldg(be1 + c0), b1 = __ldg(be1 + c0 + 1);
                float x0 = silu_f(aR0.x + aC0.x + b0 + rad0 * w0);
                float x1 = silu_f(aR0.y + aC0.y + b1 + rad0 * w1);
                float x2 = silu_f(aR1.x + aC1.x + b0 + rad1 * w0);
                float x3 = silu_f(aR1.y + aC1.y + b1 + rad1 * w1);
                XCH_STORE(ntg, x0, x1, x2, x3);
            }
        }
        __syncthreads();            // publish XCH

        // ===== layer2 (resident W2) =====
        ACC_ZERO8();
        X_CHUNK(0, 0);
        X_CHUNK(1, 0);

        // epilogue2: attention + outputs + agg + exchange
        {
            float d0 = 0.0f, d1 = 0.0f;
            #pragma unroll
            for (int nt = 0; nt < 8; nt++) {
                int c0 = (ntg0 + nt) * 8 + 2 * tq;
                float b0 = __ldg(be2 + c0), b1 = __ldg(be2 + c0 + 1);
                float wa0 = __ldg(Watt + c0), wa1 = __ldg(Watt + c0 + 1);
                acc[nt][0] = silu_f(acc[nt][0] + b0);
                acc[nt][1] = silu_f(acc[nt][1] + b1);
                acc[nt][2] = silu_f(acc[nt][2] + b0);
                acc[nt][3] = silu_f(acc[nt][3] + b1);
                d0 += acc[nt][0] * wa0 + acc[nt][1] * wa1;
                d1 += acc[nt][2] * wa0 + acc[nt][3] * wa1;
            }
            d0 += __shfl_xor_sync(0xffffffffu, d0, 1);
            d0 += __shfl_xor_sync(0xffffffffu, d0, 2);
            d1 += __shfl_xor_sync(0xffffffffu, d1, 1);
            d1 += __shfl_xor_sync(0xffffffffu, d1, 2);
            if (tq == 0) { s_red[w][g][0] = d0; s_red[w][g][1] = d1; }
            __syncthreads();        // att partials visible; layer-2 XCH reads done
            float D0 = s_red[strip * 2][g][0] + s_red[strip * 2 + 1][g][0];
            float D1 = s_red[strip * 2][g][1] + s_red[strip * 2 + 1][g][1];
            float bt = __ldg(batt);
            float att0 = 1.0f / (1.0f + __expf(-(D0 + bt)));
            float att1 = 1.0f / (1.0f + __expf(-(D1 + bt)));
            int ra = s_row[r0], rb = s_row[r1];
            float* oA = out_ef + (size_t)(e0 + r0) * 128;
            float* oB = out_ef + (size_t)(e0 + r1) * 128;
            #pragma unroll
            for (int nt = 0; nt < 8; nt++) {
                int ntg = ntg0 + nt;
                int c0 = ntg * 8 + 2 * tq;
                float x0 = acc[nt][0] * att0, x1 = acc[nt][1] * att0;
                float x2 = acc[nt][2] * att1, x3 = acc[nt][3] * att1;
                if (v0) {
                    *(float2*)(oA + c0) = make_float2(x0, x1);
                    atomicAdd(&g_agg[(size_t)ra * 128 + c0], x0);
                    atomicAdd(&g_agg[(size_t)ra * 128 + c0 + 1], x1);
                }
                if (v1) {
                    *(float2*)(oB + c0) = make_float2(x2, x3);
                    atomicAdd(&g_agg[(size_t)rb * 128 + c0], x2);
                    atomicAdd(&g_agg[(size_t)rb * 128 + c0 + 1], x3);
                }
                XCH_STORE(ntg, x0, x1, x2, x3);
            }
        }
        __syncthreads();            // publish XCH for layer3

        // ===== layer3 (resident Wc) =====
        ACC_ZERO8();
        X_CHUNK(0, WC_BASE);
        X_CHUNK(1, WC_BASE);
        {
            float d0 = 0.0f, d1 = 0.0f;
            #pragma unroll
            for (int nt = 0; nt < 8; nt++) {
                int c0 = (ntg0 + nt) * 8 + 2 * tq;
                float b0 = __ldg(bc1 + c0), b1 = __ldg(bc1 + c0 + 1);
                float wc0 = __ldg(Wc2 + c0), wc1 = __ldg(Wc2 + c0 + 1);
                d0 += silu_f(acc[nt][0] + b0) * wc0 + silu_f(acc[nt][1] + b1) * wc1;
                d1 += silu_f(acc[nt][2] + b0) * wc0 + silu_f(acc[nt][3] + b1) * wc1;
            }
            d0 += __shfl_xor_sync(0xffffffffu, d0, 1);
            d0 += __shfl_xor_sync(0xffffffffu, d0, 2);
            d1 += __shfl_xor_sync(0xffffffffu, d1, 1);
            d1 += __shfl_xor_sync(0xffffffffu, d1, 2);
            if (tq == 0) { s_red[w][g][0] = d0; s_red[w][g][1] = d1; }
            __syncthreads();
            if (nhalf == 0 && tq == 0) {
                float cw0 = s_red[w][g][0] + s_red[w + 1][g][0];
                float cw1 = s_red[w][g][1] + s_red[w + 1][g][1];
                #pragma unroll
                for (int i = 0; i < 2; i++) {
                    int rr = i ? r1 : r0;
                    bool vv = i ? v1 : v0;
                    float cw = i ? cw1 : cw0;
                    if (vv) {
                        int rn = s_row[rr];
                        #pragma unroll
                        for (int q = 0; q < 3; q++) {
                            float tr = s_cd[rr * 3 + q] * cw;
                            tr = fminf(fmaxf(tr, -10.0f), 10.0f);
                            atomicAdd(&g_tsum[rn * 3 + q], tr);
                        }
                        atomicAdd(&g_cnt[rn], 1.0f);
                    }
                }
            }
        }
    }
}

__global__ void __launch_bounds__(256, 2) node_tc_kernel(
    const float* __restrict__ h, const float* __restrict__ coord,
    const float* __restrict__ bn1, const float* __restrict__ bn2,
    float* __restrict__ out_h, float* __restrict__ out_c, int N)
{
    extern __shared__ __align__(1024) char smB[];
    const uns su = smem_u32(smB);
    const int XBv = XB_NODE;
    const int t = threadIdx.x;
    const int w = t >> 5, l = t & 31;
    const int g = l >> 2, tq = l & 3;
    const int strip = w >> 1, nhalf = w & 1;
    const int ntg0 = nhalf * 8;
    const int n0 = blockIdx.x * TM;
    const uns b_row = (uns)((l & 7) * 128 + ((l >> 3) & 1) * 16);

    LOADB_A(g_N1H, g_N1L, 0, 0, 0);
    LOADB_A(g_N1H, g_N1L, 1, 1, 0);

    const int r0 = strip * 16 + g, r1 = r0 + 8;
    const int nA = min(n0 + r0, N - 1), nB = min(n0 + r1, N - 1);
    const bool v0 = (n0 + r0) < N, v1 = (n0 + r1) < N;

    const float* pH0 = h + (size_t)nA * 128;
    const float* pH1 = h + (size_t)nB * 128;
    const float* pG0 = g_agg + (size_t)nA * 128;
    const float* pG1 = g_agg + (size_t)nB * 128;

    float acc[8][4];
    ACC_ZERO8();

    // ===== layer1 (4 chunks: 0,1 from h; 2,3 from g_agg) =====
    CP_WAIT(1); __syncthreads();
    L1_CHUNK(0, 0, pH0, pH1);
    __syncthreads();
    LOADB_A(g_N1H, g_N1L, 2, 0, 0);
    CP_WAIT(1); __syncthreads();
    L1_CHUNK(1, 1, pH0, pH1);
    __syncthreads();
    LOADB_A(g_N1H, g_N1L, 3, 1, 0);
    CP_WAIT(1); __syncthreads();
    L1_CHUNK(2, 0, pG0, pG1);
    __syncthreads();
    LOADB_A(g_N2H, g_N2L, 0, 0, 0);   // cross-layer prefetch
    CP_WAIT(1); __syncthreads();
    L1_CHUNK(3, 1, pG0, pG1);

    {
        #pragma unroll
        for (int nt = 0; nt < 8; nt++) {
            int ntg = ntg0 + nt;
            int c0 = ntg * 8 + 2 * tq;
            float b0 = __ldg(bn1 + c0), b1 = __ldg(bn1 + c0 + 1);
            float x0 = silu_f(acc[nt][0] + b0);
            float x1 = silu_f(acc[nt][1] + b1);
            float x2 = silu_f(acc[nt][2] + b0);
            float x3 = silu_f(acc[nt][3] + b1);
            XCH_STORE(ntg, x0, x1, x2, x3);
        }
    }
    __syncthreads();
    LOADB_A(g_N2H, g_N2L, 1, 1, 0);

    // ===== layer2 (2 chunks) =====
    ACC_ZERO8();
    CP_WAIT(1); __syncthreads();
    X_CHUNK(0, 0);
    CP_WAIT(0); __syncthreads();
    X_CHUNK(1, 0);

    {
        #pragma unroll
        for (int nt = 0; nt < 8; nt++) {
            int c0 = (ntg0 + nt) * 8 + 2 * tq;
            float b0 = __ldg(bn2 + c0), b1 = __ldg(bn2 + c0 + 1);
            if (v0) {
                float2 hv = *(const float2*)(h + (size_t)nA * 128 + c0);
                *(float2*)(out_h + (size_t)nA * 128 + c0) =
                    make_float2(hv.x + acc[nt][0] + b0, hv.y + acc[nt][1] + b1);
            }
            if (v1) {
                float2 hv = *(const float2*)(h + (size_t)nB * 128 + c0);
                *(float2*)(out_h + (size_t)nB * 128 + c0) =
                    make_float2(hv.x + acc[nt][2] + b0, hv.y + acc[nt][3] + b1);
            }
        }
    }

    if (t < TM) {
        int n = n0 + t;
        if (n < N) {
            float c = fmaxf(g_cnt[n], 1.0f);
            #pragma unroll
            for (int q = 0; q < 3; q++) {
                float m = g_tsum[n * 3 + q] / c;
                m = fminf(fmaxf(m, -10.0f), 10.0f);
                out_c[n * 3 + q] = coord[n * 3 + q] + m;
            }
        }
    }
}

extern "C" void kernel_launch(void* const* d_in, const int* in_sizes, int n_in,
                              void* d_out, int out_size) {
    const float* h     = (const float*)d_in[0];
    const int*   ei    = (const int*)d_in[1];
    const float* coord = (const float*)d_in[2];
    const float* We1  = (const float*)d_in[3];
    const float* be1  = (const float*)d_in[4];
    const float* We2  = (const float*)d_in[5];
    const float* be2  = (const float*)d_in[6];
    const float* Watt = (const float*)d_in[7];
    const float* batt = (const float*)d_in[8];
    const float* Wc1  = (const float*)d_in[9];
    const float* bc1  = (const float*)d_in[10];
    const float* Wc2  = (const float*)d_in[11];
    const float* Wn1  = (const float*)d_in[12];
    const float* bn1  = (const float*)d_in[13];
    const float* Wn2  = (const float*)d_in[14];
    const float* bn2  = (const float*)d_in[15];

    int N = in_sizes[0] / D;
    int E = in_sizes[1] / 2;

    float* out   = (float*)d_out;
    float* out_h = out;
    float* out_c = out + (size_t)N * D;
    float* out_e = out_c + (size_t)N * 3;

    cudaFuncSetAttribute(pre_h_kernel, cudaFuncAttributeMaxDynamicSharedMemorySize, SMEM_PRE);
    cudaFuncSetAttribute(edge_tc_kernel, cudaFuncAttributeMaxDynamicSharedMemorySize, SMEM_EDGE);
    cudaFuncSetAttribute(node_tc_kernel, cudaFuncAttributeMaxDynamicSharedMemorySize, SMEM_NODE);

    zero_kernel<<<1024, 256>>>(N);
    prep_kernel<<<64, 512>>>(We1, We2, Wc1, Wn1, Wn2);

    int nbn = (N + TM - 1) / TM;
    pre_h_kernel<<<nbn, 256, SMEM_PRE>>>(h, N);

    int nTiles = (E + TM - 1) / TM;
    int nbe = 296;                 // 2 waves at 1 CTA/SM
    if (nbe > nTiles) nbe = nTiles;
    edge_tc_kernel<<<nbe, 256, SMEM_EDGE>>>(ei, coord, be1, be2,
                                            Watt, batt, bc1, Wc2, out_e, E, nTiles);
    node_tc_kernel<<<nbn, 256, SMEM_NODE>>>(h, coord, bn1, bn2, out_h, out_c, N);
}

// round 16
// speedup vs baseline: 1.7170x; 1.7170x over previous
#include <cuda_runtime.h>
#include <cuda_fp16.h>

#define D 128
#define MAXN 50176
#define TM 64
#define NB 16384          // bytes per B buffer (128x64 fp16)
#define SM_XCH 32768      // per-thread frag exchange: 256 * 144 B
#define SMEM_DYN (32768 + 256 * 144)
#define SMEM_PRE 32768

typedef unsigned uns;

__device__ float g_agg[MAXN * D];
__device__ float g_tsum[MAXN * 3];
__device__ float g_cnt[MAXN];
__device__ float g_Hr[MAXN * D];   // h @ We1[0:128]
__device__ float g_Hc[MAXN * D];   // h @ We1[128:256]

// prepped W^T fp16 (hi only): [chunk][n=128][kc=64]
__device__ __half g_W1H[4 * 8192];
__device__ __half g_W2H[2 * 8192];
__device__ __half g_WcH[2 * 8192];
__device__ __half g_N1H[4 * 8192];
__device__ __half g_N2H[2 * 8192];
__device__ float g_W1last[128];

__device__ __forceinline__ float silu_f(float x) { return x / (1.0f + __expf(-x)); }
__device__ __forceinline__ uns sw128(uns o) { return o ^ ((o >> 3) & 0x70); }

__device__ __forceinline__ uns smem_u32(const void* p) {
    uns a;
    asm("{ .reg .u64 t; cvta.to.shared.u64 t, %1; cvt.u32.u64 %0, t; }" : "=r"(a) : "l"(p));
    return a;
}
// fp16 hi/lo split: hi = f16x2(a,b), lo = f16x2(a-hi.a, b-hi.b)
__device__ __forceinline__ void split2(float a, float b, uns& hi, uns& lo) {
    __half2 hp = __float22half2_rn(make_float2(a, b));
    float2 fb = __half22float2(hp);
    __half2 lp = __float22half2_rn(make_float2(a - fb.x, b - fb.y));
    hi = *(uns*)&hp; lo = *(uns*)&lp;
}
__device__ __forceinline__ void ldm_x2(uns r[2], uns addr) {
    asm volatile("ldmatrix.sync.aligned.m8n8.x2.shared.b16 {%0,%1}, [%2];"
        : "=r"(r[0]), "=r"(r[1]) : "r"(addr));
}
__device__ __forceinline__ void mma16816(float c[4], const uns a[4], const uns b[2]) {
    asm volatile("mma.sync.aligned.m16n8k16.row.col.f32.f16.f16.f32 "
        "{%0,%1,%2,%3}, {%4,%5,%6,%7}, {%8,%9}, {%0,%1,%2,%3};"
        : "+f"(c[0]), "+f"(c[1]), "+f"(c[2]), "+f"(c[3])
        : "r"(a[0]), "r"(a[1]), "r"(a[2]), "r"(a[3]), "r"(b[0]), "r"(b[1]));
}

// ------------------------------------------------------------------
__global__ void __launch_bounds__(256) zero_kernel(int N) {
    int i = blockIdx.x * blockDim.x + threadIdx.x;
    int stride = gridDim.x * blockDim.x;
    for (int k = i; k < N * D; k += stride) g_agg[k] = 0.0f;
    for (int k = i; k < N * 3; k += stride) g_tsum[k] = 0.0f;
    for (int k = i; k < N; k += stride) g_cnt[k] = 0.0f;
}

__global__ void __launch_bounds__(512) prep_kernel(
    const float* __restrict__ We1, const float* __restrict__ We2,
    const float* __restrict__ Wc1, const float* __restrict__ Wn1,
    const float* __restrict__ Wn2)
{
    int id = blockIdx.x * blockDim.x + threadIdx.x;  // 0..32767
    int c = id >> 13, r = id & 8191, n = r >> 6, kc = r & 63;
    int src = (c * 64 + kc) * 128 + n;
    {
        g_W1H[id] = __float2half(We1[src]);
        g_N1H[id] = __float2half(Wn1[src]);
    }
    if (id < 2 * 8192) {
        g_W2H[id] = __float2half(We2[src]);
        g_WcH[id] = __float2half(Wc1[src]);
        g_N2H[id] = __float2half(Wn2[src]);
    }
    if (id < 128) g_W1last[id] = We1[256 * 128 + id];
}

// ---- common macros (t, su, smB, b_row, ntg0, acc in scope) ----
#define LOADB_A(gH, c, buf)                                                   \
    {                                                                         \
        _Pragma("unroll")                                                     \
        for (int i0 = 0; i0 < 4; i0++) {                                      \
            int i = t + i0 * 256;                                             \
            uns dst = sw128((uns)((i >> 3) * 128 + (i & 7) * 16));            \
            const uint4* s1 = (const uint4*)(gH) + (c) * 1024 + i;            \
            asm volatile("cp.async.cg.shared.global [%0], [%1], 16;"          \
                :: "r"(su + (buf) * NB + dst),                                \
                   "l"((unsigned long long)__cvta_generic_to_global(s1)) : "memory"); \
        }                                                                     \
        asm volatile("cp.async.commit_group;" ::: "memory");                  \
    }

#define CP_WAIT(n) asm volatile("cp.async.wait_group %0;" :: "n"(n) : "memory")

// 8 nt-tiles (64 cols), 2 groups of 4; 2 chains: ah*bh + al*bh
#define MMA_NT8(ah, al, bufb)                                                 \
    _Pragma("unroll")                                                         \
    for (int ng = 0; ng < 2; ng++) {                                          \
        uns b4[4][2];                                                         \
        _Pragma("unroll")                                                     \
        for (int j = 0; j < 4; j++) {                                         \
            uns bsw = sw128(b_row + (uns)((ntg0 + ng * 4 + j) * 1024) + (uns)(ks * 32)); \
            ldm_x2(b4[j], su + (bufb) * NB + bsw);                            \
        }                                                                     \
        _Pragma("unroll")                                                     \
        for (int j = 0; j < 4; j++) mma16816(acc[ng * 4 + j], ah, b4[j]);     \
        _Pragma("unroll")                                                     \
        for (int j = 0; j < 4; j++) mma16816(acc[ng * 4 + j], al, b4[j]);     \
    }

#define ACC_ZERO8()                                                           \
    _Pragma("unroll")                                                         \
    for (int nt = 0; nt < 8; nt++)                                            \
        _Pragma("unroll")                                                     \
        for (int j = 0; j < 4; j++) acc[nt][j] = 0.0f;

#define A_FRAGS_FROM_GLOBAL(pA, pB, k0, ah, al)                               \
    {                                                                         \
        float2 vA0 = *(const float2*)((pA) + (k0));                           \
        float2 vA1 = *(const float2*)((pA) + (k0) + 8);                       \
        float2 vB0 = *(const float2*)((pB) + (k0));                           \
        float2 vB1 = *(const float2*)((pB) + (k0) + 8);                       \
        split2(vA0.x, vA0.y, ah[0], al[0]);                                   \
        split2(vB0.x, vB0.y, ah[1], al[1]);                                   \
        split2(vA1.x, vA1.y, ah[2], al[2]);                                   \
        split2(vB1.x, vB1.y, ah[3], al[3]);                                   \
    }

// layer-1-style chunk: A from global rows, k-offset = (c&1)*64
#define L1_CHUNK(c, bufb, pA, pB)                                             \
    _Pragma("unroll")                                                         \
    for (int ks = 0; ks < 4; ks++) {                                          \
        uns ah[4], al[4];                                                     \
        A_FRAGS_FROM_GLOBAL(pA, pB, ((c) & 1) * 64 + 2 * tq + ks * 16, ah, al); \
        MMA_NT8(ah, al, bufb);                                                \
    }

// XCH-layer chunk: A frags from lane-aligned exchange region
#define X_CHUNK(c, bufb)                                                      \
    _Pragma("unroll")                                                         \
    for (int ks = 0; ks < 4; ks++) {                                          \
        const int kt = (c) * 4 + ks;                                          \
        const int owner = (t & ~32) | (((c) & 1) << 5);                       \
        const char* xp = smB + SM_XCH + owner * 144 + (kt & 3) * 16;          \
        uint4 hv = *(const uint4*)xp;                                         \
        uint4 lv = *(const uint4*)(xp + 64);                                  \
        uns ah[4] = {hv.x, hv.y, hv.z, hv.w};                                 \
        uns al[4] = {lv.x, lv.y, lv.z, lv.w};                                 \
        MMA_NT8(ah, al, bufb);                                                \
    }

#define XCH_STORE(ntg, x0, x1, x2, x3)                                        \
    {                                                                         \
        uns h0, l0, h1, l1;                                                   \
        split2(x0, x1, h0, l0);                                               \
        split2(x2, x3, h1, l1);                                               \
        char* xp = smB + SM_XCH + t * 144 + ((((ntg) >> 1) & 3) * 16) + (((ntg) & 1) * 8); \
        *(uint2*)xp = make_uint2(h0, h1);                                     \
        *(uint2*)(xp + 64) = make_uint2(l0, l1);                              \
    }

// ------------------------------------------------------------------
// per-node precompute: Hr = h @ We1[0:128], Hc = h @ We1[128:256]
__global__ void __launch_bounds__(256, 2) pre_h_kernel(
    const float* __restrict__ h, int N)
{
    extern __shared__ __align__(1024) char smB[];
    const uns su = smem_u32(smB);
    const int t = threadIdx.x;
    const int w = t >> 5, l = t & 31;
    const int g = l >> 2, tq = l & 3;
    const int strip = w >> 1, nhalf = w & 1;
    const int ntg0 = nhalf * 8;
    const int n0 = blockIdx.x * TM;
    const uns b_row = (uns)((l & 7) * 128 + ((l >> 3) & 1) * 16);

    LOADB_A(g_W1H, 0, 0);
    LOADB_A(g_W1H, 1, 1);

    const int r0 = strip * 16 + g, r1 = r0 + 8;
    const int nA = min(n0 + r0, N - 1), nB = min(n0 + r1, N - 1);
    const bool v0 = (n0 + r0) < N, v1 = (n0 + r1) < N;
    const float* pH0 = h + (size_t)nA * 128;
    const float* pH1 = h + (size_t)nB * 128;

    float acc[8][4];

    // ---- Hr (weight chunks 0,1) ----
    ACC_ZERO8();
    CP_WAIT(1); __syncthreads();
    L1_CHUNK(0, 0, pH0, pH1);
    __syncthreads();
    LOADB_A(g_W1H, 2, 0);
    CP_WAIT(1); __syncthreads();
    L1_CHUNK(1, 1, pH0, pH1);
    {
        #pragma unroll
        for (int nt = 0; nt < 8; nt++) {
            int c0 = (ntg0 + nt) * 8 + 2 * tq;
            if (v0) *(float2*)(g_Hr + (size_t)nA * 128 + c0) = make_float2(acc[nt][0], acc[nt][1]);
            if (v1) *(float2*)(g_Hr + (size_t)nB * 128 + c0) = make_float2(acc[nt][2], acc[nt][3]);
        }
    }
    __syncthreads();
    LOADB_A(g_W1H, 3, 1);

    // ---- Hc (weight chunks 2,3) ----
    ACC_ZERO8();
    CP_WAIT(1); __syncthreads();
    L1_CHUNK(0, 0, pH0, pH1);
    CP_WAIT(0); __syncthreads();
    L1_CHUNK(1, 1, pH0, pH1);
    {
        #pragma unroll
        for (int nt = 0; nt < 8; nt++) {
            int c0 = (ntg0 + nt) * 8 + 2 * tq;
            if (v0) *(float2*)(g_Hc + (size_t)nA * 128 + c0) = make_float2(acc[nt][0], acc[nt][1]);
            if (v1) *(float2*)(g_Hc + (size_t)nB * 128 + c0) = make_float2(acc[nt][2], acc[nt][3]);
        }
    }
}

__global__ void __launch_bounds__(256, 2) edge_tc_kernel(
    const int* __restrict__ ei, const float* __restrict__ coord,
    const float* __restrict__ be1, const float* __restrict__ be2,
    const float* __restrict__ Watt, const float* __restrict__ batt,
    const float* __restrict__ bc1, const float* __restrict__ Wc2,
    float* __restrict__ out_ef, int E)
{
    extern __shared__ __align__(1024) char smB[];  // [Bh0][Bh1][xch]
    __shared__ int s_row[TM], s_col[TM];
    __shared__ float s_rad[TM], s_cd[TM * 3];
    __shared__ float s_red[8][8][2];

    const uns su = smem_u32(smB);
    const int t = threadIdx.x;
    const int w = t >> 5, l = t & 31;
    const int g = l >> 2, tq = l & 3;
    const int strip = w >> 1, nhalf = w & 1;
    const int ntg0 = nhalf * 8;
    const int e0 = blockIdx.x * TM;
    const uns b_row = (uns)((l & 7) * 128 + ((l >> 3) & 1) * 16);

    // start W2 loads immediately
    LOADB_A(g_W2H, 0, 0);
    LOADB_A(g_W2H, 1, 1);

    if (t < TM) {
        int e = min(e0 + t, E - 1);
        int r = ei[e], c = ei[(size_t)E + e];
        s_row[t] = r; s_col[t] = c;
        float dx = coord[r * 3 + 0] - coord[c * 3 + 0];
        float dy = coord[r * 3 + 1] - coord[c * 3 + 1];
        float dz = coord[r * 3 + 2] - coord[c * 3 + 2];
        s_cd[t * 3 + 0] = dx; s_cd[t * 3 + 1] = dy; s_cd[t * 3 + 2] = dz;
        s_rad[t] = dx * dx + dy * dy + dz * dz;
    }
    __syncthreads();

    const int r0 = strip * 16 + g, r1 = r0 + 8;
    const bool v0 = (e0 + r0) < E, v1 = (e0 + r1) < E;

    float acc[8][4];

    // ===== layer1 via gather: silu(Hr[row]+Hc[col]+be1+rad*W1last) -> XCH =====
    {
        const float* hr0 = g_Hr + (size_t)s_row[r0] * 128;
        const float* hc0 = g_Hc + (size_t)s_col[r0] * 128;
        const float* hr1 = g_Hr + (size_t)s_row[r1] * 128;
        const float* hc1 = g_Hc + (size_t)s_col[r1] * 128;
        float rad0 = s_rad[r0], rad1 = s_rad[r1];
        #pragma unroll
        for (int nt = 0; nt < 8; nt++) {
            int ntg = ntg0 + nt;
            int c0 = ntg * 8 + 2 * tq;
            float2 aR0 = *(const float2*)(hr0 + c0);
            float2 aC0 = *(const float2*)(hc0 + c0);
            float2 aR1 = *(const float2*)(hr1 + c0);
            float2 aC1 = *(const float2*)(hc1 + c0);
            float w0 = g_W1last[c0], w1 = g_W1last[c0 + 1];
            float b0 = __ldg(be1 + c0), b1 = __ldg(be1 + c0 + 1);
            float x0 = silu_f(aR0.x + aC0.x + b0 + rad0 * w0);
            float x1 = silu_f(aR0.y + aC0.y + b1 + rad0 * w1);
            float x2 = silu_f(aR1.x + aC1.x + b0 + rad1 * w0);
            float x3 = silu_f(aR1.y + aC1.y + b1 + rad1 * w1);
            XCH_STORE(ntg, x0, x1, x2, x3);
        }
    }
    __syncthreads();                // publish XCH

    // ===== layer2 (2 chunks) =====
    ACC_ZERO8();
    CP_WAIT(1); __syncthreads();
    X_CHUNK(0, 0);
    __syncthreads();
    LOADB_A(g_WcH, 0, 0);           // cross-layer prefetch
    CP_WAIT(1); __syncthreads();
    X_CHUNK(1, 1);

    // epilogue2: attention + outputs + agg + exchange
    {
        float d0 = 0.0f, d1 = 0.0f;
        #pragma unroll
        for (int nt = 0; nt < 8; nt++) {
            int c0 = (ntg0 + nt) * 8 + 2 * tq;
            float b0 = __ldg(be2 + c0), b1 = __ldg(be2 + c0 + 1);
            float wa0 = __ldg(Watt + c0), wa1 = __ldg(Watt + c0 + 1);
            acc[nt][0] = silu_f(acc[nt][0] + b0);
            acc[nt][1] = silu_f(acc[nt][1] + b1);
            acc[nt][2] = silu_f(acc[nt][2] + b0);
            acc[nt][3] = silu_f(acc[nt][3] + b1);
            d0 += acc[nt][0] * wa0 + acc[nt][1] * wa1;
            d1 += acc[nt][2] * wa0 + acc[nt][3] * wa1;
        }
        d0 += __shfl_xor_sync(0xffffffffu, d0, 1);
        d0 += __shfl_xor_sync(0xffffffffu, d0, 2);
        d1 += __shfl_xor_sync(0xffffffffu, d1, 1);
        d1 += __shfl_xor_sync(0xffffffffu, d1, 2);
        if (tq == 0) { s_red[w][g][0] = d0; s_red[w][g][1] = d1; }
        __syncthreads();            // att partials visible; layer-2 frag reads done
        LOADB_A(g_WcH, 1, 1);       // overlap with long epilogue
        float D0 = s_red[strip * 2][g][0] + s_red[strip * 2 + 1][g][0];
        float D1 = s_red[strip * 2][g][1] + s_red[strip * 2 + 1][g][1];
        float bt = __ldg(batt);
        float att0 = 1.0f / (1.0f + __expf(-(D0 + bt)));
        float att1 = 1.0f / (1.0f + __expf(-(D1 + bt)));
        int ra = s_row[r0], rb = s_row[r1];
        float* oA = out_ef + (size_t)(e0 + r0) * 128;
        float* oB = out_ef + (size_t)(e0 + r1) * 128;
        #pragma unroll
        for (int nt = 0; nt < 8; nt++) {
            int ntg = ntg0 + nt;
            int c0 = ntg * 8 + 2 * tq;
            float x0 = acc[nt][0] * att0, x1 = acc[nt][1] * att0;
            float x2 = acc[nt][2] * att1, x3 = acc[nt][3] * att1;
            if (v0) {
                *(float2*)(oA + c0) = make_float2(x0, x1);
                atomicAdd(&g_agg[(size_t)ra * 128 + c0], x0);
                atomicAdd(&g_agg[(size_t)ra * 128 + c0 + 1], x1);
            }
            if (v1) {
                *(float2*)(oB + c0) = make_float2(x2, x3);
                atomicAdd(&g_agg[(size_t)rb * 128 + c0], x2);
                atomicAdd(&g_agg[(size_t)rb * 128 + c0 + 1], x3);
            }
            XCH_STORE(ntg, x0, x1, x2, x3);
        }
    }

    // ===== layer3 (coord, 2 chunks) =====
    ACC_ZERO8();
    CP_WAIT(1); __syncthreads();    // Wc c0 ready; XCH published
    X_CHUNK(0, 0);
    CP_WAIT(0); __syncthreads();    // Wc c1 ready
    X_CHUNK(1, 1);
    {
        float d0 = 0.0f, d1 = 0.0f;
        #pragma unroll
        for (int nt = 0; nt < 8; nt++) {
            int c0 = (ntg0 + nt) * 8 + 2 * tq;
            float b0 = __ldg(bc1 + c0), b1 = __ldg(bc1 + c0 + 1);
            float wc0 = __ldg(Wc2 + c0), wc1 = __ldg(Wc2 + c0 + 1);
            d0 += silu_f(acc[nt][0] + b0) * wc0 + silu_f(acc[nt][1] + b1) * wc1;
            d1 += silu_f(acc[nt][2] + b0) * wc0 + silu_f(acc[nt][3] + b1) * wc1;
        }
        d0 += __shfl_xor_sync(0xffffffffu, d0, 1);
        d0 += __shfl_xor_sync(0xffffffffu, d0, 2);
        d1 += __shfl_xor_sync(0xffffffffu, d1, 1);
        d1 += __shfl_xor_sync(0xffffffffu, d1, 2);
        if (tq == 0) { s_red[w][g][0] = d0; s_red[w][g][1] = d1; }
        __syncthreads();
        if (nhalf == 0 && tq == 0) {
            float cw0 = s_red[w][g][0] + s_red[w + 1][g][0];
            float cw1 = s_red[w][g][1] + s_red[w + 1][g][1];
            #pragma unroll
            for (int i = 0; i < 2; i++) {
                int rr = i ? r1 : r0;
                bool vv = i ? v1 : v0;
                float cw = i ? cw1 : cw0;
                if (vv) {
                    int rn = s_row[rr];
                    #pragma unroll
                    for (int q = 0; q < 3; q++) {
                        float tr = s_cd[rr * 3 + q] * cw;
                        tr = fminf(fmaxf(tr, -10.0f), 10.0f);
                        atomicAdd(&g_tsum[rn * 3 + q], tr);
                    }
                    atomicAdd(&g_cnt[rn], 1.0f);
                }
            }
        }
    }
}

__global__ void __launch_bounds__(256, 2) node_tc_kernel(
    const float* __restrict__ h, const float* __restrict__ coord,
    const float* __restrict__ bn1, const float* __restrict__ bn2,
    float* __restrict__ out_h, float* __restrict__ out_c, int N)
{
    extern __shared__ __align__(1024) char smB[];
    const uns su = smem_u32(smB);
    const int t = threadIdx.x;
    const int w = t >> 5, l = t & 31;
    const int g = l >> 2, tq = l & 3;
    const int strip = w >> 1, nhalf = w & 1;
    const int ntg0 = nhalf * 8;
    const int n0 = blockIdx.x * TM;
    const uns b_row = (uns)((l & 7) * 128 + ((l >> 3) & 1) * 16);

    LOADB_A(g_N1H, 0, 0);
    LOADB_A(g_N1H, 1, 1);

    const int r0 = strip * 16 + g, r1 = r0 + 8;
    const int nA = min(n0 + r0, N - 1), nB = min(n0 + r1, N - 1);
    const bool v0 = (n0 + r0) < N, v1 = (n0 + r1) < N;

    const float* pH0 = h + (size_t)nA * 128;
    const float* pH1 = h + (size_t)nB * 128;
    const float* pG0 = g_agg + (size_t)nA * 128;
    const float* pG1 = g_agg + (size_t)nB * 128;

    float acc[8][4];
    ACC_ZERO8();

    // ===== layer1 (4 chunks: 0,1 from h; 2,3 from g_agg) =====
    CP_WAIT(1); __syncthreads();
    L1_CHUNK(0, 0, pH0, pH1);
    __syncthreads();
    LOADB_A(g_N1H, 2, 0);
    CP_WAIT(1); __syncthreads();
    L1_CHUNK(1, 1, pH0, pH1);
    __syncthreads();
    LOADB_A(g_N1H, 3, 1);
    CP_WAIT(1); __syncthreads();
    L1_CHUNK(2, 0, pG0, pG1);
    __syncthreads();
    LOADB_A(g_N2H, 0, 0);          // cross-layer prefetch
    CP_WAIT(1); __syncthreads();
    L1_CHUNK(3, 1, pG0, pG1);

    {
        #pragma unroll
        for (int nt = 0; nt < 8; nt++) {
            int ntg = ntg0 + nt;
            int c0 = ntg * 8 + 2 * tq;
            float b0 = __ldg(bn1 + c0), b1 = __ldg(bn1 + c0 + 1);
            float x0 = silu_f(acc[nt][0] + b0);
            float x1 = silu_f(acc[nt][1] + b1);
            float x2 = silu_f(acc[nt][2] + b0);
            float x3 = silu_f(acc[nt][3] + b1);
            XCH_STORE(ntg, x0, x1, x2, x3);
        }
    }
    __syncthreads();
    LOADB_A(g_N2H, 1, 1);

    // ===== layer2 (2 chunks) =====
    ACC_ZERO8();
    CP_WAIT(1); __syncthreads();
    X_CHUNK(0, 0);
    CP_WAIT(0); __syncthreads();
    X_CHUNK(1, 1);

    {
        #pragma unroll
        for (int nt = 0; nt < 8; nt++) {
            int c0 = (ntg0 + nt) * 8 + 2 * tq;
            float b0 = __ldg(bn2 + c0), b1 = __ldg(bn2 + c0 + 1);
            if (v0) {
                float2 hv = *(const float2*)(h + (size_t)nA * 128 + c0);
                *(float2*)(out_h + (size_t)nA * 128 + c0) =
                    make_float2(hv.x + acc[nt][0] + b0, hv.y + acc[nt][1] + b1);
            }
            if (v1) {
                float2 hv = *(const float2*)(h + (size_t)nB * 128 + c0);
                *(float2*)(out_h + (size_t)nB * 128 + c0) =
                    make_float2(hv.x + acc[nt][2] + b0, hv.y + acc[nt][3] + b1);
            }
        }
    }

    if (t < TM) {
        int n = n0 + t;
        if (n < N) {
            float c = fmaxf(g_cnt[n], 1.0f);
            #pragma unroll
            for (int q = 0; q < 3; q++) {
                float m = g_tsum[n * 3 + q] / c;
                m = fminf(fmaxf(m, -10.0f), 10.0f);
                out_c[n * 3 + q] = coord[n * 3 + q] + m;
            }
        }
    }
}

extern "C" void kernel_launch(void* const* d_in, const int* in_sizes, int n_in,
                              void* d_out, int out_size) {
    const float* h     = (const float*)d_in[0];
    const int*   ei    = (const int*)d_in[1];
    const float* coord = (const float*)d_in[2];
    const float* We1  = (const float*)d_in[3];
    const float* be1  = (const float*)d_in[4];
    const float* We2  = (const float*)d_in[5];
    const float* be2  = (const float*)d_in[6];
    const float* Watt = (const float*)d_in[7];
    const float* batt = (const float*)d_in[8];
    const float* Wc1  = (const float*)d_in[9];
    const float* bc1  = (const float*)d_in[10];
    const float* Wc2  = (const float*)d_in[11];
    const float* Wn1  = (const float*)d_in[12];
    const float* bn1  = (const float*)d_in[13];
    const float* Wn2  = (const float*)d_in[14];
    const float* bn2  = (const float*)d_in[15];

    int N = in_sizes[0] / D;
    int E = in_sizes[1] / 2;

    float* out   = (float*)d_out;
    float* out_h = out;
    float* out_c = out + (size_t)N * D;
    float* out_e = out_c + (size_t)N * 3;

    cudaFuncSetAttribute(pre_h_kernel, cudaFuncAttributeMaxDynamicSharedMemorySize, SMEM_PRE);
    cudaFuncSetAttribute(edge_tc_kernel, cudaFuncAttributeMaxDynamicSharedMemorySize, SMEM_DYN);
    cudaFuncSetAttribute(node_tc_kernel, cudaFuncAttributeMaxDynamicSharedMemorySize, SMEM_DYN);

    zero_kernel<<<1024, 256>>>(N);
    prep_kernel<<<64, 512>>>(We1, We2, Wc1, Wn1, Wn2);

    int nbn = (N + TM - 1) / TM;
    pre_h_kernel<<<nbn, 256, SMEM_PRE>>>(h, N);

    int nbe = (E + TM - 1) / TM;
    edge_tc_kernel<<<nbe, 256, SMEM_DYN>>>(ei, coord, be1, be2,
                                           Watt, batt, bc1, Wc2, out_e, E);
    node_tc_kernel<<<nbn, 256, SMEM_DYN>>>(h, coord, bn1, bn2, out_h, out_c, N);
}

// round 17
// speedup vs baseline: 1.7453x; 1.0165x over previous
#include <cuda_runtime.h>
#include <cuda_fp16.h>

#define D 128
#define MAXN 50176
#define TM 64
#define NB 16384          // bytes per B buffer (128x64 fp16)
#define SM_XCH 32768      // per-thread frag exchange: 256 * 144 B
#define SMEM_DYN (32768 + 256 * 144)
#define SMEM_PRE 32768

typedef unsigned uns;

__device__ float g_agg[MAXN * D];
__device__ float g_tsum[MAXN * 3];
__device__ float g_cnt[MAXN];
__device__ float g_Hr[MAXN * D];   // h @ We1[0:128]
__device__ float g_Hc[MAXN * D];   // h @ We1[128:256]

// prepped W^T fp16 (hi only): [chunk][n=128][kc=64]
__device__ __half g_W1H[4 * 8192];
__device__ __half g_W2H[2 * 8192];
__device__ __half g_WcH[2 * 8192];
__device__ __half g_N1H[4 * 8192];
__device__ __half g_N2H[2 * 8192];
__device__ float g_W1last[128];

__device__ __forceinline__ float silu_f(float x) { return x / (1.0f + __expf(-x)); }
__device__ __forceinline__ uns sw128(uns o) { return o ^ ((o >> 3) & 0x70); }

__device__ __forceinline__ uns smem_u32(const void* p) {
    uns a;
    asm("{ .reg .u64 t; cvta.to.shared.u64 t, %1; cvt.u32.u64 %0, t; }" : "=r"(a) : "l"(p));
    return a;
}
// vectorized global reduction: one instruction adds a pair (8B-aligned)
__device__ __forceinline__ void red_add_v2(float* addr, float a, float b) {
    asm volatile("red.global.add.v2.f32 [%0], {%1, %2};"
                 :: "l"(addr), "f"(a), "f"(b) : "memory");
}
// fp16 hi/lo split: hi = f16x2(a,b), lo = f16x2(a-hi.a, b-hi.b)
__device__ __forceinline__ void split2(float a, float b, uns& hi, uns& lo) {
    __half2 hp = __float22half2_rn(make_float2(a, b));
    float2 fb = __half22float2(hp);
    __half2 lp = __float22half2_rn(make_float2(a - fb.x, b - fb.y));
    hi = *(uns*)&hp; lo = *(uns*)&lp;
}
__device__ __forceinline__ void ldm_x2(uns r[2], uns addr) {
    asm volatile("ldmatrix.sync.aligned.m8n8.x2.shared.b16 {%0,%1}, [%2];"
        : "=r"(r[0]), "=r"(r[1]) : "r"(addr));
}
__device__ __forceinline__ void mma16816(float c[4], const uns a[4], const uns b[2]) {
    asm volatile("mma.sync.aligned.m16n8k16.row.col.f32.f16.f16.f32 "
        "{%0,%1,%2,%3}, {%4,%5,%6,%7}, {%8,%9}, {%0,%1,%2,%3};"
        : "+f"(c[0]), "+f"(c[1]), "+f"(c[2]), "+f"(c[3])
        : "r"(a[0]), "r"(a[1]), "r"(a[2]), "r"(a[3]), "r"(b[0]), "r"(b[1]));
}

// ------------------------------------------------------------------
__global__ void __launch_bounds__(256) zero_kernel(int N) {
    int i = blockIdx.x * blockDim.x + threadIdx.x;
    int stride = gridDim.x * blockDim.x;
    for (int k = i; k < N * D; k += stride) g_agg[k] = 0.0f;
    for (int k = i; k < N * 3; k += stride) g_tsum[k] = 0.0f;
    for (int k = i; k < N; k += stride) g_cnt[k] = 0.0f;
}

__global__ void __launch_bounds__(512) prep_kernel(
    const float* __restrict__ We1, const float* __restrict__ We2,
    const float* __restrict__ Wc1, const float* __restrict__ Wn1,
    const float* __restrict__ Wn2)
{
    int id = blockIdx.x * blockDim.x + threadIdx.x;  // 0..32767
    int c = id >> 13, r = id & 8191, n = r >> 6, kc = r & 63;
    int src = (c * 64 + kc) * 128 + n;
    {
        g_W1H[id] = __float2half(We1[src]);
        g_N1H[id] = __float2half(Wn1[src]);
    }
    if (id < 2 * 8192) {
        g_W2H[id] = __float2half(We2[src]);
        g_WcH[id] = __float2half(Wc1[src]);
        g_N2H[id] = __float2half(Wn2[src]);
    }
    if (id < 128) g_W1last[id] = We1[256 * 128 + id];
}

// ---- common macros (t, su, smB, b_row, ntg0, acc in scope) ----
#define LOADB_A(gH, c, buf)                                                   \
    {                                                                         \
        _Pragma("unroll")                                                     \
        for (int i0 = 0; i0 < 4; i0++) {                                      \
            int i = t + i0 * 256;                                             \
            uns dst = sw128((uns)((i >> 3) * 128 + (i & 7) * 16));            \
            const uint4* s1 = (const uint4*)(gH) + (c) * 1024 + i;            \
            asm volatile("cp.async.cg.shared.global [%0], [%1], 16;"          \
                :: "r"(su + (buf) * NB + dst),                                \
                   "l"((unsigned long long)__cvta_generic_to_global(s1)) : "memory"); \
        }                                                                     \
        asm volatile("cp.async.commit_group;" ::: "memory");                  \
    }

#define CP_WAIT(n) asm volatile("cp.async.wait_group %0;" :: "n"(n) : "memory")

// 8 nt-tiles (64 cols), 2 groups of 4; 2 chains: ah*bh + al*bh
#define MMA_NT8(ah, al, bufb)                                                 \
    _Pragma("unroll")                                                         \
    for (int ng = 0; ng < 2; ng++) {                                          \
        uns b4[4][2];                                                         \
        _Pragma("unroll")                                                     \
        for (int j = 0; j < 4; j++) {                                         \
            uns bsw = sw128(b_row + (uns)((ntg0 + ng * 4 + j) * 1024) + (uns)(ks * 32)); \
            ldm_x2(b4[j], su + (bufb) * NB + bsw);                            \
        }                                                                     \
        _Pragma("unroll")                                                     \
        for (int j = 0; j < 4; j++) mma16816(acc[ng * 4 + j], ah, b4[j]);     \
        _Pragma("unroll")                                                     \
        for (int j = 0; j < 4; j++) mma16816(acc[ng * 4 + j], al, b4[j]);     \
    }

#define ACC_ZERO8()                                                           \
    _Pragma("unroll")                                                         \
    for (int nt = 0; nt < 8; nt++)                                            \
        _Pragma("unroll")                                                     \
        for (int j = 0; j < 4; j++) acc[nt][j] = 0.0f;

#define A_FRAGS_FROM_GLOBAL(pA, pB, k0, ah, al)                               \
    {                                                                         \
        float2 vA0 = *(const float2*)((pA) + (k0));                           \
        float2 vA1 = *(const float2*)((pA) + (k0) + 8);                       \
        float2 vB0 = *(const float2*)((pB) + (k0));                           \
        float2 vB1 = *(const float2*)((pB) + (k0) + 8);                       \
        split2(vA0.x, vA0.y, ah[0], al[0]);                                   \
        split2(vB0.x, vB0.y, ah[1], al[1]);                                   \
        split2(vA1.x, vA1.y, ah[2], al[2]);                                   \
        split2(vB1.x, vB1.y, ah[3], al[3]);                                   \
    }

// layer-1-style chunk: A from global rows, k-offset = (c&1)*64
#define L1_CHUNK(c, bufb, pA, pB)                                             \
    _Pragma("unroll")                                                         \
    for (int ks = 0; ks < 4; ks++) {                                          \
        uns ah[4], al[4];                                                     \
        A_FRAGS_FROM_GLOBAL(pA, pB, ((c) & 1) * 64 + 2 * tq + ks * 16, ah, al); \
        MMA_NT8(ah, al, bufb);                                                \
    }

// XCH-layer chunk: A frags from lane-aligned exchange region
#define X_CHUNK(c, bufb)                                                      \
    _Pragma("unroll")                                                         \
    for (int ks = 0; ks < 4; ks++) {                                          \
        const int kt = (c) * 4 + ks;                                          \
        const int owner = (t & ~32) | (((c) & 1) << 5);                       \
        const char* xp = smB + SM_XCH + owner * 144 + (kt & 3) * 16;          \
        uint4 hv = *(const uint4*)xp;                                         \
        uint4 lv = *(const uint4*)(xp + 64);                                  \
        uns ah[4] = {hv.x, hv.y, hv.z, hv.w};                                 \
        uns al[4] = {lv.x, lv.y, lv.z, lv.w};                                 \
        MMA_NT8(ah, al, bufb);                                                \
    }

#define XCH_STORE(ntg, x0, x1, x2, x3)                                        \
    {                                                                         \
        uns h0, l0, h1, l1;                                                   \
        split2(x0, x1, h0, l0);                                               \
        split2(x2, x3, h1, l1);                                               \
        char* xp = smB + SM_XCH + t * 144 + ((((ntg) >> 1) & 3) * 16) + (((ntg) & 1) * 8); \
        *(uint2*)xp = make_uint2(h0, h1);                                     \
        *(uint2*)(xp + 64) = make_uint2(l0, l1);                              \
    }

// ------------------------------------------------------------------
// per-node precompute: Hr = h @ We1[0:128], Hc = h @ We1[128:256]
__global__ void __launch_bounds__(256, 2) pre_h_kernel(
    const float* __restrict__ h, int N)
{
    extern __shared__ __align__(1024) char smB[];
    const uns su = smem_u32(smB);
    const int t = threadIdx.x;
    const int w = t >> 5, l = t & 31;
    const int g = l >> 2, tq = l & 3;
    const int strip = w >> 1, nhalf = w & 1;
    const int ntg0 = nhalf * 8;
    const int n0 = blockIdx.x * TM;
    const uns b_row = (uns)((l & 7) * 128 + ((l >> 3) & 1) * 16);

    LOADB_A(g_W1H, 0, 0);
    LOADB_A(g_W1H, 1, 1);

    const int r0 = strip * 16 + g, r1 = r0 + 8;
    const int nA = min(n0 + r0, N - 1), nB = min(n0 + r1, N - 1);
    const bool v0 = (n0 + r0) < N, v1 = (n0 + r1) < N;
    const float* pH0 = h + (size_t)nA * 128;
    const float* pH1 = h + (size_t)nB * 128;

    float acc[8][4];

    // ---- Hr (weight chunks 0,1) ----
    ACC_ZERO8();
    CP_WAIT(1); __syncthreads();
    L1_CHUNK(0, 0, pH0, pH1);
    __syncthreads();
    LOADB_A(g_W1H, 2, 0);
    CP_WAIT(1); __syncthreads();
    L1_CHUNK(1, 1, pH0, pH1);
    {
        #pragma unroll
        for (int nt = 0; nt < 8; nt++) {
            int c0 = (ntg0 + nt) * 8 + 2 * tq;
            if (v0) *(float2*)(g_Hr + (size_t)nA * 128 + c0) = make_float2(acc[nt][0], acc[nt][1]);
            if (v1) *(float2*)(g_Hr + (size_t)nB * 128 + c0) = make_float2(acc[nt][2], acc[nt][3]);
        }
    }
    __syncthreads();
    LOADB_A(g_W1H, 3, 1);

    // ---- Hc (weight chunks 2,3) ----
    ACC_ZERO8();
    CP_WAIT(1); __syncthreads();
    L1_CHUNK(0, 0, pH0, pH1);
    CP_WAIT(0); __syncthreads();
    L1_CHUNK(1, 1, pH0, pH1);
    {
        #pragma unroll
        for (int nt = 0; nt < 8; nt++) {
            int c0 = (ntg0 + nt) * 8 + 2 * tq;
            if (v0) *(float2*)(g_Hc + (size_t)nA * 128 + c0) = make_float2(acc[nt][0], acc[nt][1]);
            if (v1) *(float2*)(g_Hc + (size_t)nB * 128 + c0) = make_float2(acc[nt][2], acc[nt][3]);
        }
    }
}

__global__ void __launch_bounds__(256, 2) edge_tc_kernel(
    const int* __restrict__ ei, const float* __restrict__ coord,
    const float* __restrict__ be1, const float* __restrict__ be2,
    const float* __restrict__ Watt, const float* __restrict__ batt,
    const float* __restrict__ bc1, const float* __restrict__ Wc2,
    float* __restrict__ out_ef, int E)
{
    extern __shared__ __align__(1024) char smB[];  // [Bh0][Bh1][xch]
    __shared__ int s_row[TM], s_col[TM];
    __shared__ float s_rad[TM], s_cd[TM * 3];
    __shared__ float s_red[8][8][2];

    const uns su = smem_u32(smB);
    const int t = threadIdx.x;
    const int w = t >> 5, l = t & 31;
    const int g = l >> 2, tq = l & 3;
    const int strip = w >> 1, nhalf = w & 1;
    const int ntg0 = nhalf * 8;
    const int e0 = blockIdx.x * TM;
    const uns b_row = (uns)((l & 7) * 128 + ((l >> 3) & 1) * 16);

    // start W2 loads immediately
    LOADB_A(g_W2H, 0, 0);
    LOADB_A(g_W2H, 1, 1);

    if (t < TM) {
        int e = min(e0 + t, E - 1);
        int r = ei[e], c = ei[(size_t)E + e];
        s_row[t] = r; s_col[t] = c;
        float dx = coord[r * 3 + 0] - coord[c * 3 + 0];
        float dy = coord[r * 3 + 1] - coord[c * 3 + 1];
        float dz = coord[r * 3 + 2] - coord[c * 3 + 2];
        s_cd[t * 3 + 0] = dx; s_cd[t * 3 + 1] = dy; s_cd[t * 3 + 2] = dz;
        s_rad[t] = dx * dx + dy * dy + dz * dz;
    }
    __syncthreads();

    const int r0 = strip * 16 + g, r1 = r0 + 8;
    const bool v0 = (e0 + r0) < E, v1 = (e0 + r1) < E;

    float acc[8][4];

    // ===== layer1 via gather: silu(Hr[row]+Hc[col]+be1+rad*W1last) -> XCH =====
    {
        const float* hr0 = g_Hr + (size_t)s_row[r0] * 128;
        const float* hc0 = g_Hc + (size_t)s_col[r0] * 128;
        const float* hr1 = g_Hr + (size_t)s_row[r1] * 128;
        const float* hc1 = g_Hc + (size_t)s_col[r1] * 128;
        float rad0 = s_rad[r0], rad1 = s_rad[r1];
        #pragma unroll
        for (int nt = 0; nt < 8; nt++) {
            int ntg = ntg0 + nt;
            int c0 = ntg * 8 + 2 * tq;
            float2 aR0 = *(const float2*)(hr0 + c0);
            float2 aC0 = *(const float2*)(hc0 + c0);
            float2 aR1 = *(const float2*)(hr1 + c0);
            float2 aC1 = *(const float2*)(hc1 + c0);
            float w0 = g_W1last[c0], w1 = g_W1last[c0 + 1];
            float b0 = __ldg(be1 + c0), b1 = __ldg(be1 + c0 + 1);
            float x0 = silu_f(aR0.x + aC0.x + b0 + rad0 * w0);
            float x1 = silu_f(aR0.y + aC0.y + b1 + rad0 * w1);
            float x2 = silu_f(aR1.x + aC1.x + b0 + rad1 * w0);
            float x3 = silu_f(aR1.y + aC1.y + b1 + rad1 * w1);
            XCH_STORE(ntg, x0, x1, x2, x3);
        }
    }
    __syncthreads();                // publish XCH

    // ===== layer2 (2 chunks) =====
    ACC_ZERO8();
    CP_WAIT(1); __syncthreads();
    X_CHUNK(0, 0);
    __syncthreads();
    LOADB_A(g_WcH, 0, 0);           // cross-layer prefetch
    CP_WAIT(1); __syncthreads();
    X_CHUNK(1, 1);

    // epilogue2: attention + outputs + agg (vectorized red) + exchange
    {
        float d0 = 0.0f, d1 = 0.0f;
        #pragma unroll
        for (int nt = 0; nt < 8; nt++) {
            int c0 = (ntg0 + nt) * 8 + 2 * tq;
            float b0 = __ldg(be2 + c0), b1 = __ldg(be2 + c0 + 1);
            float wa0 = __ldg(Watt + c0), wa1 = __ldg(Watt + c0 + 1);
            acc[nt][0] = silu_f(acc[nt][0] + b0);
            acc[nt][1] = silu_f(acc[nt][1] + b1);
            acc[nt][2] = silu_f(acc[nt][2] + b0);
            acc[nt][3] = silu_f(acc[nt][3] + b1);
            d0 += acc[nt][0] * wa0 + acc[nt][1] * wa1;
            d1 += acc[nt][2] * wa0 + acc[nt][3] * wa1;
        }
        d0 += __shfl_xor_sync(0xffffffffu, d0, 1);
        d0 += __shfl_xor_sync(0xffffffffu, d0, 2);
        d1 += __shfl_xor_sync(0xffffffffu, d1, 1);
        d1 += __shfl_xor_sync(0xffffffffu, d1, 2);
        if (tq == 0) { s_red[w][g][0] = d0; s_red[w][g][1] = d1; }
        __syncthreads();            // att partials visible; layer-2 frag reads done
        LOADB_A(g_WcH, 1, 1);       // overlap with long epilogue
        float D0 = s_red[strip * 2][g][0] + s_red[strip * 2 + 1][g][0];
        float D1 = s_red[strip * 2][g][1] + s_red[strip * 2 + 1][g][1];
        float bt = __ldg(batt);
        float att0 = 1.0f / (1.0f + __expf(-(D0 + bt)));
        float att1 = 1.0f / (1.0f + __expf(-(D1 + bt)));
        int ra = s_row[r0], rb = s_row[r1];
        float* oA = out_ef + (size_t)(e0 + r0) * 128;
        float* oB = out_ef + (size_t)(e0 + r1) * 128;
        #pragma unroll
        for (int nt = 0; nt < 8; nt++) {
            int ntg = ntg0 + nt;
            int c0 = ntg * 8 + 2 * tq;
            float x0 = acc[nt][0] * att0, x1 = acc[nt][1] * att0;
            float x2 = acc[nt][2] * att1, x3 = acc[nt][3] * att1;
            if (v0) {
                *(float2*)(oA + c0) = make_float2(x0, x1);
                red_add_v2(&g_agg[(size_t)ra * 128 + c0], x0, x1);
            }
            if (v1) {
                *(float2*)(oB + c0) = make_float2(x2, x3);
                red_add_v2(&g_agg[(size_t)rb * 128 + c0], x2, x3);
            }
            XCH_STORE(ntg, x0, x1, x2, x3);
        }
    }

    // ===== layer3 (coord, 2 chunks) =====
    ACC_ZERO8();
    CP_WAIT(1); __syncthreads();    // Wc c0 ready; XCH published
    X_CHUNK(0, 0);
    CP_WAIT(0); __syncthreads();    // Wc c1 ready
    X_CHUNK(1, 1);
    {
        float d0 = 0.0f, d1 = 0.0f;
        #pragma unroll
        for (int nt = 0; nt < 8; nt++) {
            int c0 = (ntg0 + nt) * 8 + 2 * tq;
            float b0 = __ldg(bc1 + c0), b1 = __ldg(bc1 + c0 + 1);
            float wc0 = __ldg(Wc2 + c0), wc1 = __ldg(Wc2 + c0 + 1);
            d0 += silu_f(acc[nt][0] + b0) * wc0 + silu_f(acc[nt][1] + b1) * wc1;
            d1 += silu_f(acc[nt][2] + b0) * wc0 + silu_f(acc[nt][3] + b1) * wc1;
        }
        d0 += __shfl_xor_sync(0xffffffffu, d0, 1);
        d0 += __shfl_xor_sync(0xffffffffu, d0, 2);
        d1 += __shfl_xor_sync(0xffffffffu, d1, 1);
        d1 += __shfl_xor_sync(0xffffffffu, d1, 2);
        if (tq == 0) { s_red[w][g][0] = d0; s_red[w][g][1] = d1; }
        __syncthreads();
        if (nhalf == 0 && tq == 0) {
            float cw0 = s_red[w][g][0] + s_red[w + 1][g][0];
            float cw1 = s_red[w][g][1] + s_red[w + 1][g][1];
            #pragma unroll
            for (int i = 0; i < 2; i++) {
                int rr = i ? r1 : r0;
                bool vv = i ? v1 : v0;
                float cw = i ? cw1 : cw0;
                if (vv) {
                    int rn = s_row[rr];
                    float t0 = fminf(fmaxf(s_cd[rr * 3 + 0] * cw, -10.0f), 10.0f);
                    float t1 = fminf(fmaxf(s_cd[rr * 3 + 1] * cw, -10.0f), 10.0f);
                    float t2 = fminf(fmaxf(s_cd[rr * 3 + 2] * cw, -10.0f), 10.0f);
                    if ((rn & 1) == 0) {
                        red_add_v2(&g_tsum[rn * 3 + 0], t0, t1);
                        atomicAdd(&g_tsum[rn * 3 + 2], t2);
                    } else {
                        atomicAdd(&g_tsum[rn * 3 + 0], t0);
                        red_add_v2(&g_tsum[rn * 3 + 1], t1, t2);
                    }
                    atomicAdd(&g_cnt[rn], 1.0f);
                }
            }
        }
    }
}

__global__ void __launch_bounds__(256, 2) node_tc_kernel(
    const float* __restrict__ h, const float* __restrict__ coord,
    const float* __restrict__ bn1, const float* __restrict__ bn2,
    float* __restrict__ out_h, float* __restrict__ out_c, int N)
{
    extern __shared__ __align__(1024) char smB[];
    const uns su = smem_u32(smB);
    const int t = threadIdx.x;
    const int w = t >> 5, l = t & 31;
    const int g = l >> 2, tq = l & 3;
    const int strip = w >> 1, nhalf = w & 1;
    const int ntg0 = nhalf * 8;
    const int n0 = blockIdx.x * TM;
    const uns b_row = (uns)((l & 7) * 128 + ((l >> 3) & 1) * 16);

    LOADB_A(g_N1H, 0, 0);
    LOADB_A(g_N1H, 1, 1);

    const int r0 = strip * 16 + g, r1 = r0 + 8;
    const int nA = min(n0 + r0, N - 1), nB = min(n0 + r1, N - 1);
    const bool v0 = (n0 + r0) < N, v1 = (n0 + r1) < N;

    const float* pH0 = h + (size_t)nA * 128;
    const float* pH1 = h + (size_t)nB * 128;
    const float* pG0 = g_agg + (size_t)nA * 128;
    const float* pG1 = g_agg + (size_t)nB * 128;

    float acc[8][4];
    ACC_ZERO8();

    // ===== layer1 (4 chunks: 0,1 from h; 2,3 from g_agg) =====
    CP_WAIT(1); __syncthreads();
    L1_CHUNK(0, 0, pH0, pH1);
    __syncthreads();
    LOADB_A(g_N1H, 2, 0);
    CP_WAIT(1); __syncthreads();
    L1_CHUNK(1, 1, pH0, pH1);
    __syncthreads();
    LOADB_A(g_N1H, 3, 1);
    CP_WAIT(1); __syncthreads();
    L1_CHUNK(2, 0, pG0, pG1);
    __syncthreads();
    LOADB_A(g_N2H, 0, 0);          // cross-layer prefetch
    CP_WAIT(1); __syncthreads();
    L1_CHUNK(3, 1, pG0, pG1);

    {
        #pragma unroll
        for (int nt = 0; nt < 8; nt++) {
            int ntg = ntg0 + nt;
            int c0 = ntg * 8 + 2 * tq;
            float b0 = __ldg(bn1 + c0), b1 = __ldg(bn1 + c0 + 1);
            float x0 = silu_f(acc[nt][0] + b0);
            float x1 = silu_f(acc[nt][1] + b1);
            float x2 = silu_f(acc[nt][2] + b0);
            float x3 = silu_f(acc[nt][3] + b1);
            XCH_STORE(ntg, x0, x1, x2, x3);
        }
    }
    __syncthreads();
    LOADB_A(g_N2H, 1, 1);

    // ===== layer2 (2 chunks) =====
    ACC_ZERO8();
    CP_WAIT(1); __syncthreads();
    X_CHUNK(0, 0);
    CP_WAIT(0); __syncthreads();
    X_CHUNK(1, 1);

    {
        #pragma unroll
        for (int nt = 0; nt < 8; nt++) {
            int c0 = (ntg0 + nt) * 8 + 2 * tq;
            float b0 = __ldg(bn2 + c0), b1 = __ldg(bn2 + c0 + 1);
            if (v0) {
                float2 hv = *(const float2*)(h + (size_t)nA * 128 + c0);
                *(float2*)(out_h + (size_t)nA * 128 + c0) =
                    make_float2(hv.x + acc[nt][0] + b0, hv.y + acc[nt][1] + b1);
            }
            if (v1) {
                float2 hv = *(const float2*)(h + (size_t)nB * 128 + c0);
                *(float2*)(out_h + (size_t)nB * 128 + c0) =
                    make_float2(hv.x + acc[nt][2] + b0, hv.y + acc[nt][3] + b1);
            }
        }
    }

    if (t < TM) {
        int n = n0 + t;
        if (n < N) {
            float c = fmaxf(g_cnt[n], 1.0f);
            #pragma unroll
            for (int q = 0; q < 3; q++) {
                float m = g_tsum[n * 3 + q] / c;
                m = fminf(fmaxf(m, -10.0f), 10.0f);
                out_c[n * 3 + q] = coord[n * 3 + q] + m;
            }
        }
    }
}

extern "C" void kernel_launch(void* const* d_in, const int* in_sizes, int n_in,
                              void* d_out, int out_size) {
    const float* h     = (const float*)d_in[0];
    const int*   ei    = (const int*)d_in[1];
    const float* coord = (const float*)d_in[2];
    const float* We1  = (const float*)d_in[3];
    const float* be1  = (const float*)d_in[4];
    const float* We2  = (const float*)d_in[5];
    const float* be2  = (const float*)d_in[6];
    const float* Watt = (const float*)d_in[7];
    const float* batt = (const float*)d_in[8];
    const float* Wc1  = (const float*)d_in[9];
    const float* bc1  = (const float*)d_in[10];
    const float* Wc2  = (const float*)d_in[11];
    const float* Wn1  = (const float*)d_in[12];
    const float* bn1  = (const float*)d_in[13];
    const float* Wn2  = (const float*)d_in[14];
    const float* bn2  = (const float*)d_in[15];

    int N = in_sizes[0] / D;
    int E = in_sizes[1] / 2;

    float* out   = (float*)d_out;
    float* out_h = out;
    float* out_c = out + (size_t)N * D;
    float* out_e = out_c + (size_t)N * 3;

    cudaFuncSetAttribute(pre_h_kernel, cudaFuncAttributeMaxDynamicSharedMemorySize, SMEM_PRE);
    cudaFuncSetAttribute(edge_tc_kernel, cudaFuncAttributeMaxDynamicSharedMemorySize, SMEM_DYN);
    cudaFuncSetAttribute(node_tc_kernel, cudaFuncAttributeMaxDynamicSharedMemorySize, SMEM_DYN);

    zero_kernel<<<1024, 256>>>(N);
    prep_kernel<<<64, 512>>>(We1, We2, Wc1, Wn1, Wn2);

    int nbn = (N + TM - 1) / TM;
    pre_h_kernel<<<nbn, 256, SMEM_PRE>>>(h, N);

    int nbe = (E + TM - 1) / TM;
    edge_tc_kernel<<<nbe, 256, SMEM_DYN>>>(ei, coord, be1, be2,
                                           Watt, batt, bc1, Wc2, out_e, E);
    node_tc_kernel<<<nbn, 256, SMEM_DYN>>>(h, coord, bn1, bn2, out_h, out_c, N);
}